// round 8
// baseline (speedup 1.0000x reference)
#include <cuda_runtime.h>
#include <cstdint>

#define C_ 128
#define F_ 1024
#define BK 16
#define NCHUNK (F_/BK)               // 64
#define NTHREADS 128
#define P 20                         // 16-k row + pad4: frag banks (20g+tig)%32 distinct
#define A_FLOATS (128*P)             // 2560
#define B_FLOATS (64*P)              // 1280
#define SMEM_BYTES ((2*A_FLOATS + 2*B_FLOATS)*4)   // 30720 -> 4 CTAs/SM

__device__ __forceinline__ uint32_t tf32r(float v) {
    uint32_t r;
    asm("cvt.rna.tf32.f32 %0, %1;" : "=r"(r) : "f"(v));
    return r;
}

__device__ __forceinline__ void mma_tf32(float d[4], const uint32_t a[4], const uint32_t b[2]) {
    asm volatile(
        "mma.sync.aligned.m16n8k8.row.col.f32.tf32.tf32.f32 "
        "{%0,%1,%2,%3}, {%4,%5,%6,%7}, {%8,%9}, {%0,%1,%2,%3};"
        : "+f"(d[0]), "+f"(d[1]), "+f"(d[2]), "+f"(d[3])
        : "r"(a[0]), "r"(a[1]), "r"(a[2]), "r"(a[3]), "r"(b[0]), "r"(b[1]));
}

__device__ __forceinline__ void sts4(float* p, float4 v) {
    uint32_t x0 = tf32r(v.x), x1 = tf32r(v.y), x2 = tf32r(v.z), x3 = tf32r(v.w);
    *reinterpret_cast<uint4*>(p) = make_uint4(x0, x1, x2, x3);
}

__global__ void __launch_bounds__(NTHREADS, 4) cwlinear_mma_kernel(
    const float* __restrict__ x, const float* __restrict__ W,
    const float* __restrict__ bias, float* __restrict__ out)
{
    extern __shared__ float sm[];
    const int tid = threadIdx.x;
    const int wid = tid >> 5, lid = tid & 31;
    const int wm = wid >> 1, wn = wid & 1;          // warp grid 2(m) x 2(n); warp tile 64x32
    const int g = lid >> 2, tig = lid & 3;          // quad layout
    const int gt = blockIdx.x;                      // 0..7 g-tile
    const int c  = blockIdx.y;                      // 0..127 channel
    const int g0 = gt * 128;

    // ---- staging maps: A = 128 rows x 4 f4 (4/thread), B = 64 rows x 4 f4 (2/thread)
    const float* Wg = W + ((size_t)c * F_ + g0) * F_;
    const float* xg = x + (size_t)c * F_;
    int a_go[4], a_so[4];
#pragma unroll
    for (int i = 0; i < 4; i++) {
        int f4 = tid + i * NTHREADS;                // 0..511
        int r = f4 >> 2, c4 = f4 & 3;
        a_so[i] = r * P + c4 * 4;
        a_go[i] = r * F_ + c4 * 4;
    }
    int b_go[2], b_so[2];
#pragma unroll
    for (int i = 0; i < 2; i++) {
        int f4 = tid + i * NTHREADS;                // 0..255
        int r = f4 >> 2, c4 = f4 & 3;
        b_so[i] = r * P + c4 * 4;
        b_go[i] = r * C_ * F_ + c4 * 4;             // x[r][c][k]
    }

    float d[4][4][4];
#pragma unroll
    for (int mt = 0; mt < 4; mt++)
#pragma unroll
        for (int nt = 0; nt < 4; nt++)
#pragma unroll
            for (int j = 0; j < 4; j++) d[mt][nt][j] = 0.0f;

    // ---- prologue prefetch (chunk 0)
    float4 ra[4], rb[2];
#pragma unroll
    for (int i = 0; i < 4; i++) ra[i] = __ldcs((const float4*)(Wg + a_go[i]));
#pragma unroll
    for (int i = 0; i < 2; i++) rb[i] = __ldg((const float4*)(xg + b_go[i]));

    // fragment bases (float indices)
    const int afrag0 = (wm * 64 + g) * P + tig;     // +mt*16*P ; +8P ; +4 ; +8s
    const int bfrag0 = (wn * 32 + g) * P + tig;     // +nt*8*P ; +4 ; +8s

    for (int kc = 0; kc < NCHUNK; kc++) {
        const int buf = kc & 1;
        float* Ab = sm + buf * A_FLOATS;
        float* Bb = sm + 2 * A_FLOATS + buf * B_FLOATS;

#pragma unroll
        for (int i = 0; i < 4; i++) sts4(Ab + a_so[i], ra[i]);
#pragma unroll
        for (int i = 0; i < 2; i++) sts4(Bb + b_so[i], rb[i]);
        __syncthreads();

        if (kc + 1 < NCHUNK) {
            const int off = (kc + 1) * BK;
#pragma unroll
            for (int i = 0; i < 4; i++) ra[i] = __ldcs((const float4*)(Wg + a_go[i] + off));
#pragma unroll
            for (int i = 0; i < 2; i++) rb[i] = __ldg((const float4*)(xg + b_go[i] + off));
        }

#pragma unroll
        for (int s = 0; s < 2; s++) {               // two k=8 halves
            const int ks = s * 8;
            uint32_t af[4][4];
#pragma unroll
            for (int mt = 0; mt < 4; mt++) {
                const float* ap = Ab + afrag0 + mt * 16 * P + ks;
                af[mt][0] = __float_as_uint(ap[0]);
                af[mt][1] = __float_as_uint(ap[8 * P]);
                af[mt][2] = __float_as_uint(ap[4]);
                af[mt][3] = __float_as_uint(ap[8 * P + 4]);
            }
            uint32_t bf[4][2];
#pragma unroll
            for (int nt = 0; nt < 4; nt++) {
                const float* bp = Bb + bfrag0 + nt * 8 * P + ks;
                bf[nt][0] = __float_as_uint(bp[0]);
                bf[nt][1] = __float_as_uint(bp[4]);
            }
#pragma unroll
            for (int mt = 0; mt < 4; mt++)
#pragma unroll
                for (int nt = 0; nt < 4; nt++)
                    mma_tf32(d[mt][nt], af[mt], bf[nt]);
        }
    }

    // ---- epilogue: y[b, c, g] = d + bias[c, g]
#pragma unroll
    for (int mt = 0; mt < 4; mt++) {
        const int m0 = g0 + wm * 64 + mt * 16 + g;
        const float bv0 = bias[c * F_ + m0];
        const float bv1 = bias[c * F_ + m0 + 8];
#pragma unroll
        for (int nt = 0; nt < 4; nt++) {
            const int n0 = wn * 32 + nt * 8 + 2 * tig;
            float* o0 = out + ((size_t)n0 * C_ + c) * F_;
            float* o1 = o0 + (size_t)C_ * F_;
            o0[m0]     = d[mt][nt][0] + bv0;
            o1[m0]     = d[mt][nt][1] + bv0;
            o0[m0 + 8] = d[mt][nt][2] + bv1;
            o1[m0 + 8] = d[mt][nt][3] + bv1;
        }
    }
}

extern "C" void kernel_launch(void* const* d_in, const int* in_sizes, int n_in,
                              void* d_out, int out_size) {
    const float* x    = (const float*)d_in[0];
    const float* W    = (const float*)d_in[1];
    const float* bias = (const float*)d_in[2];
    float* out = (float*)d_out;

    cudaFuncSetAttribute(cwlinear_mma_kernel,
                         cudaFuncAttributeMaxDynamicSharedMemorySize, SMEM_BYTES);
    cwlinear_mma_kernel<<<dim3(8, C_), NTHREADS, SMEM_BYTES>>>(x, W, bias, out);
}

// round 14
// speedup vs baseline: 1.7040x; 1.7040x over previous
#include <cuda_runtime.h>
#include <cuda_pipeline_primitives.h>
#include <cstdint>

#define C_ 128
#define F_ 1024
#define BK 16
#define NCHUNK (F_/BK)               // 64
#define NTHREADS 128
#define NSTAGE 3
#define P 20                         // frag banks (20g+tig)%32 all distinct; rows 16B-aligned
#define A_FL (128*P)                 // 2560 floats
#define B_FL (64*P)                  // 1280 floats
#define STAGE_FL (A_FL + B_FL)       // 3840 floats
#define SMEM_BYTES (NSTAGE*STAGE_FL*4)   // 46080 B -> 4 CTAs/SM (184.3 KB)

__device__ __forceinline__ uint32_t tf32r(float v) {
    uint32_t r;
    asm("cvt.rna.tf32.f32 %0, %1;" : "=r"(r) : "f"(v));
    return r;
}

__device__ __forceinline__ void mma_tf32(float d[4], const uint32_t a[4], const uint32_t b[2]) {
    asm volatile(
        "mma.sync.aligned.m16n8k8.row.col.f32.tf32.tf32.f32 "
        "{%0,%1,%2,%3}, {%4,%5,%6,%7}, {%8,%9}, {%0,%1,%2,%3};"
        : "+f"(d[0]), "+f"(d[1]), "+f"(d[2]), "+f"(d[3])
        : "r"(a[0]), "r"(a[1]), "r"(a[2]), "r"(a[3]), "r"(b[0]), "r"(b[1]));
}

__global__ void __launch_bounds__(NTHREADS, 4) cwlinear_mma_kernel(
    const float* __restrict__ x, const float* __restrict__ W,
    const float* __restrict__ bias, float* __restrict__ out)
{
    extern __shared__ float sm[];

    const int tid = threadIdx.x;
    const int wid = tid >> 5, lid = tid & 31;
    const int wm = wid >> 1, wn = wid & 1;          // warp grid 2(m) x 2(n); warp tile 64x32
    const int g = lid >> 2, tig = lid & 3;
    const int gt = blockIdx.x;                      // 0..7 g-tile
    const int c  = blockIdx.y;                      // 0..127 channel
    const int g0 = gt * 128;

    const float* Wg = W + ((size_t)c * F_ + g0) * F_;
    const float* xg = x + (size_t)c * F_;

    // async-copy maps: A = 128 rows x 4 f4 (4/thread), B = 64 rows x 4 f4 (2/thread)
    int a_go[4], a_so[4];
#pragma unroll
    for (int j = 0; j < 4; j++) {
        int f4 = tid + j * NTHREADS;                // 0..511
        int r = f4 >> 2, c4 = f4 & 3;
        a_go[j] = r * F_ + c4 * 4;
        a_so[j] = r * P + c4 * 4;
    }
    int b_go[2], b_so[2];
#pragma unroll
    for (int j = 0; j < 2; j++) {
        int f4 = tid + j * NTHREADS;                // 0..255
        int r = f4 >> 2, c4 = f4 & 3;
        b_so[j] = r * P + c4 * 4;
        b_go[j] = r * (C_ * F_) + c4 * 4;           // x[r][c][k]
    }

    auto issue = [&](int stage, int kc) {
        float* sA = sm + stage * STAGE_FL;
        float* sB = sA + A_FL;
        const int ko = kc * BK;
#pragma unroll
        for (int j = 0; j < 4; j++)
            __pipeline_memcpy_async(sA + a_so[j], Wg + a_go[j] + ko, 16);
#pragma unroll
        for (int j = 0; j < 2; j++)
            __pipeline_memcpy_async(sB + b_so[j], xg + b_go[j] + ko, 16);
    };

    float d[4][4][4];
#pragma unroll
    for (int mt = 0; mt < 4; mt++)
#pragma unroll
        for (int nt = 0; nt < 4; nt++)
#pragma unroll
            for (int j = 0; j < 4; j++) d[mt][nt][j] = 0.0f;

    // prologue: stages 0,1 in flight
    issue(0, 0); __pipeline_commit();
    issue(1, 1); __pipeline_commit();

    const int afrag0 = (wm * 64 + g) * P + tig;     // +mt*16*P ; +8P ; +4 ; +ks
    const int bfrag0 = (wn * 32 + g) * P + tig;     // +nt*8*P ; +4 ; +ks

    int stage = 0;
    for (int kc = 0; kc < NCHUNK; kc++) {
        __pipeline_wait_prior(1);                    // stage kc resident
        __syncthreads();                             // all warps see it; prev buf free

        if (kc + 2 < NCHUNK) issue((stage + 2 >= NSTAGE) ? stage + 2 - NSTAGE : stage + 2, kc + 2);
        __pipeline_commit();                         // uniform one-commit-per-iter accounting

        const float* Ab = sm + stage * STAGE_FL;
        const float* Bb = Ab + A_FL;

#pragma unroll
        for (int s = 0; s < 2; s++) {
            const int ks = s * 8;
            uint32_t af[4][4];
#pragma unroll
            for (int mt = 0; mt < 4; mt++) {
                const float* ap = Ab + afrag0 + mt * 16 * P + ks;
                af[mt][0] = tf32r(ap[0]);
                af[mt][1] = tf32r(ap[8 * P]);
                af[mt][2] = tf32r(ap[4]);
                af[mt][3] = tf32r(ap[8 * P + 4]);
            }
            uint32_t bf[4][2];
#pragma unroll
            for (int nt = 0; nt < 4; nt++) {
                const float* bp = Bb + bfrag0 + nt * 8 * P + ks;
                bf[nt][0] = tf32r(bp[0]);
                bf[nt][1] = tf32r(bp[4]);
            }
#pragma unroll
            for (int mt = 0; mt < 4; mt++)
#pragma unroll
                for (int nt = 0; nt < 4; nt++)
                    mma_tf32(d[mt][nt], af[mt], bf[nt]);
        }

        stage = (stage + 1 >= NSTAGE) ? 0 : stage + 1;
    }

    // epilogue: y[b, c, g] = d + bias[c, g]
#pragma unroll
    for (int mt = 0; mt < 4; mt++) {
        const int m0 = g0 + wm * 64 + mt * 16 + g;
        const float bv0 = bias[c * F_ + m0];
        const float bv1 = bias[c * F_ + m0 + 8];
#pragma unroll
        for (int nt = 0; nt < 4; nt++) {
            const int n0 = wn * 32 + nt * 8 + 2 * tig;
            float* o0 = out + ((size_t)n0 * C_ + c) * F_;
            float* o1 = o0 + (size_t)C_ * F_;
            o0[m0]     = d[mt][nt][0] + bv0;
            o1[m0]     = d[mt][nt][1] + bv0;
            o0[m0 + 8] = d[mt][nt][2] + bv1;
            o1[m0 + 8] = d[mt][nt][3] + bv1;
        }
    }
}

extern "C" void kernel_launch(void* const* d_in, const int* in_sizes, int n_in,
                              void* d_out, int out_size) {
    const float* x    = (const float*)d_in[0];
    const float* W    = (const float*)d_in[1];
    const float* bias = (const float*)d_in[2];
    float* out = (float*)d_out;

    cudaFuncSetAttribute(cwlinear_mma_kernel,
                         cudaFuncAttributeMaxDynamicSharedMemorySize, SMEM_BYTES);
    cwlinear_mma_kernel<<<dim3(8, C_), NTHREADS, SMEM_BYTES>>>(x, W, bias, out);
}

// round 15
// speedup vs baseline: 1.9228x; 1.1284x over previous
#include <cuda_runtime.h>
#include <cuda_pipeline_primitives.h>
#include <cstdint>

#define C_ 128
#define F_ 1024
#define BK 32
#define NCHUNK (F_/BK)               // 32
#define NTHREADS 128
#define P 36                         // 32-k row + pad4: frag banks (4g+tig)%32 all distinct
#define A_FL (128*P)                 // 4608 floats
#define B_FL (64*P)                  // 2304 floats
#define STAGE_FL (A_FL + B_FL)       // 6912 floats
#define SMEM_BYTES (2*STAGE_FL*4)    // 55296 B -> 4 CTAs/SM (221 KB)

__device__ __forceinline__ uint32_t tf32r(float v) {
    uint32_t r;
    asm("cvt.rna.tf32.f32 %0, %1;" : "=r"(r) : "f"(v));
    return r;
}

__device__ __forceinline__ void mma_tf32(float d[4], const uint32_t a[4], const uint32_t b[2]) {
    asm volatile(
        "mma.sync.aligned.m16n8k8.row.col.f32.tf32.tf32.f32 "
        "{%0,%1,%2,%3}, {%4,%5,%6,%7}, {%8,%9}, {%0,%1,%2,%3};"
        : "+f"(d[0]), "+f"(d[1]), "+f"(d[2]), "+f"(d[3])
        : "r"(a[0]), "r"(a[1]), "r"(a[2]), "r"(a[3]), "r"(b[0]), "r"(b[1]));
}

__global__ void __launch_bounds__(NTHREADS, 4) cwlinear_mma_kernel(
    const float* __restrict__ x, const float* __restrict__ W,
    const float* __restrict__ bias, float* __restrict__ out)
{
    extern __shared__ float sm[];

    const int tid = threadIdx.x;
    const int wid = tid >> 5, lid = tid & 31;
    const int wm = wid >> 1, wn = wid & 1;          // warp grid 2(m) x 2(n); warp tile 64x32
    const int g = lid >> 2, tig = lid & 3;
    const int gt = blockIdx.x;                      // 0..7 g-tile
    const int c  = blockIdx.y;                      // 0..127 channel
    const int g0 = gt * 128;

    // strided copy maps (row = tid>>3 + 16j, col f4 = tid&7)
    const int r0 = tid >> 3, c40 = (tid & 7) * 4;
    const float* aG = W + ((size_t)c * F_ + g0 + r0) * F_ + c40;  // + j*16*F_ ; + ko
    const float* bG = x + ((size_t)r0 * C_ + c) * F_ + c40;       // + j*16*C_*F_ ; + ko
    const int aS = r0 * P + c40;                                   // + j*16*P
    const int bS = aS;

    auto issue = [&](int stage, int kc) {
        float* sA = sm + stage * STAGE_FL;
        float* sB = sA + A_FL;
        const int ko = kc * BK;
#pragma unroll
        for (int j = 0; j < 8; j++)
            __pipeline_memcpy_async(sA + aS + j * (16 * P), aG + (size_t)j * (16 * F_) + ko, 16);
#pragma unroll
        for (int j = 0; j < 4; j++)
            __pipeline_memcpy_async(sB + bS + j * (16 * P), bG + (size_t)j * (16 * C_ * F_) + ko, 16);
    };

    float d[4][4][4];
#pragma unroll
    for (int mt = 0; mt < 4; mt++)
#pragma unroll
        for (int nt = 0; nt < 4; nt++)
#pragma unroll
            for (int j = 0; j < 4; j++) d[mt][nt][j] = 0.0f;

    issue(0, 0); __pipeline_commit();

    const int afrag0 = (wm * 64 + g) * P + tig;     // +mt*16*P ; +8P ; +4 ; +ks
    const int bfrag0 = (wn * 32 + g) * P + tig;     // +nt*8*P ; +4 ; +ks

    for (int kc = 0; kc < NCHUNK; kc++) {
        const int stage = kc & 1;
        __pipeline_wait_prior(0);                    // chunk kc resident (issued >=1 chunk ago)
        __syncthreads();                             // everyone done with buf^1 (chunk kc-1)

        if (kc + 1 < NCHUNK) { issue(stage ^ 1, kc + 1); __pipeline_commit(); }

        const float* Ab = sm + stage * STAGE_FL;
        const float* Bb = Ab + A_FL;

#pragma unroll
        for (int s = 0; s < 4; s++) {
            const int ks = s * 8;
            uint32_t af[4][4];
#pragma unroll
            for (int mt = 0; mt < 4; mt++) {
                const float* ap = Ab + afrag0 + mt * 16 * P + ks;
                af[mt][0] = tf32r(ap[0]);
                af[mt][1] = tf32r(ap[8 * P]);
                af[mt][2] = tf32r(ap[4]);
                af[mt][3] = tf32r(ap[8 * P + 4]);
            }
            uint32_t bf[4][2];
#pragma unroll
            for (int nt = 0; nt < 4; nt++) {
                const float* bp = Bb + bfrag0 + nt * 8 * P + ks;
                bf[nt][0] = tf32r(bp[0]);
                bf[nt][1] = tf32r(bp[4]);
            }
#pragma unroll
            for (int mt = 0; mt < 4; mt++)
#pragma unroll
                for (int nt = 0; nt < 4; nt++)
                    mma_tf32(d[mt][nt], af[mt], bf[nt]);
        }
    }

    // epilogue: y[b, c, g] = d + bias[c, g]
#pragma unroll
    for (int mt = 0; mt < 4; mt++) {
        const int m0 = g0 + wm * 64 + mt * 16 + g;
        const float bv0 = bias[c * F_ + m0];
        const float bv1 = bias[c * F_ + m0 + 8];
#pragma unroll
        for (int nt = 0; nt < 4; nt++) {
            const int n0 = wn * 32 + nt * 8 + 2 * tig;
            float* o0 = out + ((size_t)n0 * C_ + c) * F_;
            float* o1 = o0 + (size_t)C_ * F_;
            o0[m0]     = d[mt][nt][0] + bv0;
            o1[m0]     = d[mt][nt][1] + bv0;
            o0[m0 + 8] = d[mt][nt][2] + bv1;
            o1[m0 + 8] = d[mt][nt][3] + bv1;
        }
    }
}

extern "C" void kernel_launch(void* const* d_in, const int* in_sizes, int n_in,
                              void* d_out, int out_size) {
    const float* x    = (const float*)d_in[0];
    const float* W    = (const float*)d_in[1];
    const float* bias = (const float*)d_in[2];
    float* out = (float*)d_out;

    cudaFuncSetAttribute(cwlinear_mma_kernel,
                         cudaFuncAttributeMaxDynamicSharedMemorySize, SMEM_BYTES);
    cwlinear_mma_kernel<<<dim3(8, C_), NTHREADS, SMEM_BYTES>>>(x, W, bias, out);
}